// round 15
// baseline (speedup 1.0000x reference)
#include <cuda_runtime.h>

// LDDMM variational shooting RHS, Gaussian kernel, sigma=0.1. B=1, N=8192, D=3.
//   p      = clip(mom, -1, 1)
//   K_ij   = exp(-50*|x_i-x_j|^2) = exp2( (xi . xj')  + ci + cj ),
//            where xj' = 100*log2e*xj, ci = -50*log2e*|xi|^2, cj = -50*log2e*|xj|^2
//   dcp_i  = sum_j K_ij p_j
//   w_ij   = K_ij (p_i.p_j)
//   dmom_i = 100*( x_i*sum_j w_ij - sum_j w_ij x_j )
//          = 100*x_i*row - ln2 * sum_j w_ij xj'      (since xj' = 100*log2e*xj)
// Output: [dmom (N*3) | dcp (N*3)] float32.
//
// Inner loop packs TWO j-points per 64-bit register (f32x2 packed FMA,
// sm_103a FFMA2 path — only reachable via PTX). Accumulators stay packed;
// halves are summed once in the epilogue.

#define NPTS   8192
#define NSPLIT 16
#define JCHUNK (NPTS / NSPLIT)   // 512 j per block
#define JPAIRS (JCHUNK / 2)      // 256 packed pairs
#define TPB    256

#define LOG2E     1.4426950408889634f
#define LN2F      0.6931471805599453f
#define C100L2E   (100.0f * LOG2E)
#define CM50L2E   (-50.0f * LOG2E)

typedef unsigned long long u64;

// Partial accumulators per (split, i). Static device scratch (no allocation).
__device__ float4 g_partA[NSPLIT * NPTS];  // dcp0, dcp1, dcp2, row
__device__ float4 g_partB[NSPLIT * NPTS];  // a0', a1', a2' (scaled by C100L2E), pad

__device__ __forceinline__ float ex2f(float a) {
    float r;
    asm("ex2.approx.f32 %0, %1;" : "=f"(r) : "f"(a));
    return r;
}
__device__ __forceinline__ u64 pk2(float lo, float hi) {
    u64 r;
    asm("mov.b64 %0, {%1, %2};" : "=l"(r) : "f"(lo), "f"(hi));
    return r;
}
__device__ __forceinline__ float2 upk2(u64 v) {
    float2 f;
    asm("mov.b64 {%0, %1}, %2;" : "=f"(f.x), "=f"(f.y) : "l"(v));
    return f;
}
__device__ __forceinline__ u64 fma2(u64 a, u64 b, u64 c) {
    u64 r;
    asm("fma.rn.f32x2 %0, %1, %2, %3;" : "=l"(r) : "l"(a), "l"(b), "l"(c));
    return r;
}
__device__ __forceinline__ u64 mul2(u64 a, u64 b) {
    u64 r;
    asm("mul.rn.f32x2 %0, %1, %2;" : "=l"(r) : "l"(a), "l"(b));
    return r;
}
__device__ __forceinline__ u64 add2(u64 a, u64 b) {
    u64 r;
    asm("add.rn.f32x2 %0, %1, %2;" : "=l"(r) : "l"(a), "l"(b));
    return r;
}

// One packed j-pair tile entry: 64 bytes = 4x LDS.128 per iteration.
//   q0 = (xj0'_pair, xj1'_pair)   q1 = (xj2'_pair, cj_pair)   [xj' = C100L2E*xj]
//   q2 = (pj0_pair,  pj1_pair)    q3 = (pj2_pair,  pad)
struct __align__(16) JPack { ulonglong2 q0, q1, q2, q3; };

__global__ __launch_bounds__(TPB)
void lddmm_partial(const float* __restrict__ mom,
                   const float* __restrict__ x) {
    __shared__ JPack sT[JPAIRS];   // 256 * 64B = 16 KB

    const int i  = blockIdx.x * TPB + threadIdx.x;   // 0..8191
    const int s  = blockIdx.y;                       // j-split index
    const int j0 = s * JCHUNK;

    // i-point loads issued BEFORE the tile build so their L2 latency overlaps
    // the cooperative smem fill.
    const float xi0 = x[3 * i + 0];
    const float xi1 = x[3 * i + 1];
    const float xi2 = x[3 * i + 2];
    const float pi0 = fminf(fmaxf(mom[3 * i + 0], -1.0f), 1.0f);
    const float pi1 = fminf(fmaxf(mom[3 * i + 1], -1.0f), 1.0f);
    const float pi2 = fminf(fmaxf(mom[3 * i + 2], -1.0f), 1.0f);
    const float ci  = CM50L2E * fmaf(xi0, xi0, fmaf(xi1, xi1, xi2 * xi2));

    // Build packed tile. Thread handles one j; writes its scalar fields into
    // the (lo,hi)=(even j, odd j) slots of its j-pair record.
    {
        float* f = (float*)sT;
        for (int t = threadIdx.x; t < JCHUNK; t += TPB) {
            const int j   = j0 + t;
            const int jp  = t >> 1;
            const int h   = t & 1;
            const int b   = jp * 16 + h;   // float index base (+h selects lo/hi)
            const float xj0 = x[3 * j + 0];
            const float xj1 = x[3 * j + 1];
            const float xj2 = x[3 * j + 2];
            const float pj0 = fminf(fmaxf(mom[3 * j + 0], -1.0f), 1.0f);
            const float pj1 = fminf(fmaxf(mom[3 * j + 1], -1.0f), 1.0f);
            const float pj2 = fminf(fmaxf(mom[3 * j + 2], -1.0f), 1.0f);
            const float cj  = CM50L2E * fmaf(xj0, xj0, fmaf(xj1, xj1, xj2 * xj2));
            f[b +  0] = C100L2E * xj0;  f[b +  2] = C100L2E * xj1;
            f[b +  4] = C100L2E * xj2;  f[b +  6] = cj;
            f[b +  8] = pj0;            f[b + 10] = pj1;
            f[b + 12] = pj2;            f[b + 14] = 0.0f;
        }
    }
    __syncthreads();

    // Loop-invariant splats of i-data.
    const u64 xi0d = pk2(xi0, xi0), xi1d = pk2(xi1, xi1), xi2d = pk2(xi2, xi2);
    const u64 pi0d = pk2(pi0, pi0), pi1d = pk2(pi1, pi1), pi2d = pk2(pi2, pi2);
    const u64 cid  = pk2(ci, ci);

    u64 dcp0d = 0, dcp1d = 0, dcp2d = 0, rowd = 0;
    u64 a0d = 0, a1d = 0, a2d = 0;

#pragma unroll 16
    for (int t = 0; t < JPAIRS; ++t) {
        const JPack J = sT[t];           // 4x LDS.128, all-lane broadcast

        // exp2 argument: (xi . xj') + ci + cj, pure FMA chain seeded by ci+cj
        u64 d = add2(cid, J.q1.y);
        d = fma2(xi0d, J.q0.x, d);
        d = fma2(xi1d, J.q0.y, d);
        d = fma2(xi2d, J.q1.x, d);
        const float2 af = upk2(d);
        const u64 Kd = pk2(ex2f(af.x), ex2f(af.y));

        // pi . pj
        u64 pd = mul2(pi0d, J.q2.x);
        pd = fma2(pi1d, J.q2.y, pd);
        pd = fma2(pi2d, J.q3.x, pd);
        const u64 wd = mul2(Kd, pd);

        dcp0d = fma2(Kd, J.q2.x, dcp0d);
        dcp1d = fma2(Kd, J.q2.y, dcp1d);
        dcp2d = fma2(Kd, J.q3.x, dcp2d);
        rowd  = add2(rowd, wd);
        a0d   = fma2(wd, J.q0.x, a0d);   // accumulates w * xj' (scaled)
        a1d   = fma2(wd, J.q0.y, a1d);
        a2d   = fma2(wd, J.q1.x, a2d);
    }

    // Horizontal lo+hi reduction of packed accumulators.
    const float2 f0 = upk2(dcp0d), f1 = upk2(dcp1d), f2 = upk2(dcp2d);
    const float2 fr = upk2(rowd);
    const float2 g0 = upk2(a0d),  g1 = upk2(a1d),  g2 = upk2(a2d);

    g_partA[s * NPTS + i] = make_float4(f0.x + f0.y, f1.x + f1.y,
                                        f2.x + f2.y, fr.x + fr.y);
    g_partB[s * NPTS + i] = make_float4(g0.x + g0.y, g1.x + g1.y,
                                        g2.x + g2.y, 0.f);
}

__global__ __launch_bounds__(TPB)
void lddmm_reduce(const float* __restrict__ x,
                  float* __restrict__ out) {
    const int i = blockIdx.x * TPB + threadIdx.x;

    float dcp0 = 0.f, dcp1 = 0.f, dcp2 = 0.f;
    float row  = 0.f;
    float a0   = 0.f, a1 = 0.f, a2 = 0.f;   // scaled by C100L2E

#pragma unroll
    for (int s = 0; s < NSPLIT; ++s) {
        const float4 A = g_partA[s * NPTS + i];
        const float4 B = g_partB[s * NPTS + i];
        dcp0 += A.x; dcp1 += A.y; dcp2 += A.z; row += A.w;
        a0   += B.x; a1   += B.y; a2   += B.z;
    }

    const float xi0 = x[3 * i + 0];
    const float xi1 = x[3 * i + 1];
    const float xi2 = x[3 * i + 2];

    // dmom = 100*(x_i*row - a) with a = a'/(100*log2e):
    //      = 100*x_i*row - ln2 * a'
    const float r100 = 100.0f * row;
    out[3 * i + 0] = fmaf(r100, xi0, -LN2F * a0);
    out[3 * i + 1] = fmaf(r100, xi1, -LN2F * a1);
    out[3 * i + 2] = fmaf(r100, xi2, -LN2F * a2);

    out[3 * NPTS + 3 * i + 0] = dcp0;
    out[3 * NPTS + 3 * i + 1] = dcp1;
    out[3 * NPTS + 3 * i + 2] = dcp2;
}

extern "C" void kernel_launch(void* const* d_in, const int* in_sizes, int n_in,
                              void* d_out, int out_size) {
    const float* mom = (const float*)d_in[0];   // (1, 8192, 3)
    const float* x   = (const float*)d_in[1];   // (1, 8192, 3)
    float* out = (float*)d_out;                 // [dmom | dcp], 49152 floats

    dim3 grid1(NPTS / TPB, NSPLIT);             // (32, 16) blocks
    lddmm_partial<<<grid1, TPB>>>(mom, x);
    lddmm_reduce<<<NPTS / TPB, TPB>>>(x, out);
}

// round 16
// speedup vs baseline: 1.0011x; 1.0011x over previous
#include <cuda_runtime.h>

// LDDMM variational shooting RHS, Gaussian kernel, sigma=0.1. B=1, N=8192, D=3.
// Single fused kernel: j-split partial sums + threadfence-reduction epilogue.
// The last block to finish each i-column performs that column's reduction
// (fixed read order -> bit-deterministic regardless of arrival order).

#define NPTS   8192
#define NSPLIT 16
#define JCHUNK (NPTS / NSPLIT)   // 512 j per block
#define JPAIRS (JCHUNK / 2)      // 256 packed pairs
#define TPB    256
#define NIBLK  (NPTS / TPB)      // 32 i-columns

#define LOG2E     1.4426950408889634f
#define LN2F      0.6931471805599453f
#define C100L2E   (100.0f * LOG2E)
#define CM50L2E   (-50.0f * LOG2E)

typedef unsigned long long u64;

// Partial accumulators per (split, i) + arrival counters. Static scratch.
__device__ float4 g_partA[NSPLIT * NPTS];  // dcp0, dcp1, dcp2, row
__device__ float4 g_partB[NSPLIT * NPTS];  // a0', a1', a2' (scaled), pad
__device__ int    g_cnt[NIBLK];            // zero-init; reset by last block

__device__ __forceinline__ float ex2f(float a) {
    float r;
    asm("ex2.approx.f32 %0, %1;" : "=f"(r) : "f"(a));
    return r;
}
__device__ __forceinline__ u64 pk2(float lo, float hi) {
    u64 r;
    asm("mov.b64 %0, {%1, %2};" : "=l"(r) : "f"(lo), "f"(hi));
    return r;
}
__device__ __forceinline__ float2 upk2(u64 v) {
    float2 f;
    asm("mov.b64 {%0, %1}, %2;" : "=f"(f.x), "=f"(f.y) : "l"(v));
    return f;
}
__device__ __forceinline__ u64 fma2(u64 a, u64 b, u64 c) {
    u64 r;
    asm("fma.rn.f32x2 %0, %1, %2, %3;" : "=l"(r) : "l"(a), "l"(b), "l"(c));
    return r;
}
__device__ __forceinline__ u64 mul2(u64 a, u64 b) {
    u64 r;
    asm("mul.rn.f32x2 %0, %1, %2;" : "=l"(r) : "l"(a), "l"(b));
    return r;
}
__device__ __forceinline__ u64 add2(u64 a, u64 b) {
    u64 r;
    asm("add.rn.f32x2 %0, %1, %2;" : "=l"(r) : "l"(a), "l"(b));
    return r;
}

// One packed j-pair tile entry: 64 bytes = 4x LDS.128 per iteration.
//   q0 = (xj0'_pair, xj1'_pair)   q1 = (xj2'_pair, cj_pair)   [xj' = C100L2E*xj]
//   q2 = (pj0_pair,  pj1_pair)    q3 = (pj2_pair,  pad)
struct __align__(16) JPack { ulonglong2 q0, q1, q2, q3; };

__global__ __launch_bounds__(TPB)
void lddmm_fused(const float* __restrict__ mom,
                 const float* __restrict__ x,
                 float* __restrict__ out) {
    __shared__ JPack sT[JPAIRS];   // 16 KB
    __shared__ int   sLast;

    const int i  = blockIdx.x * TPB + threadIdx.x;   // 0..8191
    const int s  = blockIdx.y;                       // j-split index
    const int j0 = s * JCHUNK;

    // i-point loads before tile build (L2 latency overlapped with smem fill).
    const float xi0 = x[3 * i + 0];
    const float xi1 = x[3 * i + 1];
    const float xi2 = x[3 * i + 2];
    const float pi0 = fminf(fmaxf(mom[3 * i + 0], -1.0f), 1.0f);
    const float pi1 = fminf(fmaxf(mom[3 * i + 1], -1.0f), 1.0f);
    const float pi2 = fminf(fmaxf(mom[3 * i + 2], -1.0f), 1.0f);
    const float ci  = CM50L2E * fmaf(xi0, xi0, fmaf(xi1, xi1, xi2 * xi2));

    // Build packed tile: thread t writes j=j0+t's fields into the lo/hi slot
    // of its j-pair record.
    {
        float* f = (float*)sT;
        for (int t = threadIdx.x; t < JCHUNK; t += TPB) {
            const int j   = j0 + t;
            const int jp  = t >> 1;
            const int h   = t & 1;
            const int b   = jp * 16 + h;
            const float xj0 = x[3 * j + 0];
            const float xj1 = x[3 * j + 1];
            const float xj2 = x[3 * j + 2];
            const float pj0 = fminf(fmaxf(mom[3 * j + 0], -1.0f), 1.0f);
            const float pj1 = fminf(fmaxf(mom[3 * j + 1], -1.0f), 1.0f);
            const float pj2 = fminf(fmaxf(mom[3 * j + 2], -1.0f), 1.0f);
            const float cj  = CM50L2E * fmaf(xj0, xj0, fmaf(xj1, xj1, xj2 * xj2));
            f[b +  0] = C100L2E * xj0;  f[b +  2] = C100L2E * xj1;
            f[b +  4] = C100L2E * xj2;  f[b +  6] = cj;
            f[b +  8] = pj0;            f[b + 10] = pj1;
            f[b + 12] = pj2;            f[b + 14] = 0.0f;
        }
    }
    __syncthreads();

    // Loop-invariant splats of i-data.
    const u64 xi0d = pk2(xi0, xi0), xi1d = pk2(xi1, xi1), xi2d = pk2(xi2, xi2);
    const u64 pi0d = pk2(pi0, pi0), pi1d = pk2(pi1, pi1), pi2d = pk2(pi2, pi2);
    const u64 cid  = pk2(ci, ci);

    u64 dcp0d = 0, dcp1d = 0, dcp2d = 0, rowd = 0;
    u64 a0d = 0, a1d = 0, a2d = 0;

#pragma unroll 16
    for (int t = 0; t < JPAIRS; ++t) {
        const JPack J = sT[t];           // 4x LDS.128, all-lane broadcast

        // exp2 argument: (xi . xj') + ci + cj
        u64 d = add2(cid, J.q1.y);
        d = fma2(xi0d, J.q0.x, d);
        d = fma2(xi1d, J.q0.y, d);
        d = fma2(xi2d, J.q1.x, d);
        const float2 af = upk2(d);
        const u64 Kd = pk2(ex2f(af.x), ex2f(af.y));

        // pi . pj
        u64 pd = mul2(pi0d, J.q2.x);
        pd = fma2(pi1d, J.q2.y, pd);
        pd = fma2(pi2d, J.q3.x, pd);
        const u64 wd = mul2(Kd, pd);

        dcp0d = fma2(Kd, J.q2.x, dcp0d);
        dcp1d = fma2(Kd, J.q2.y, dcp1d);
        dcp2d = fma2(Kd, J.q3.x, dcp2d);
        rowd  = add2(rowd, wd);
        a0d   = fma2(wd, J.q0.x, a0d);   // accumulates w * xj' (scaled)
        a1d   = fma2(wd, J.q0.y, a1d);
        a2d   = fma2(wd, J.q1.x, a2d);
    }

    // Horizontal lo+hi reduction; write this split's partials.
    {
        const float2 f0 = upk2(dcp0d), f1 = upk2(dcp1d), f2 = upk2(dcp2d);
        const float2 fr = upk2(rowd);
        const float2 g0 = upk2(a0d),  g1 = upk2(a1d),  g2 = upk2(a2d);
        g_partA[s * NPTS + i] = make_float4(f0.x + f0.y, f1.x + f1.y,
                                            f2.x + f2.y, fr.x + fr.y);
        g_partB[s * NPTS + i] = make_float4(g0.x + g0.y, g1.x + g1.y,
                                            g2.x + g2.y, 0.f);
    }

    // Threadfence reduction: last block of this i-column reduces it.
    __threadfence();
    if (threadIdx.x == 0) {
        const int prev = atomicAdd(&g_cnt[blockIdx.x], 1);
        sLast = (prev == NSPLIT - 1);
    }
    __syncthreads();
    if (!sLast) return;

    // This block arrived last: all 16 partials for this i-column are visible.
    float dcp0 = 0.f, dcp1 = 0.f, dcp2 = 0.f, row = 0.f;
    float a0 = 0.f, a1 = 0.f, a2 = 0.f;
#pragma unroll
    for (int ss = 0; ss < NSPLIT; ++ss) {
        const float4 A = g_partA[ss * NPTS + i];
        const float4 B = g_partB[ss * NPTS + i];
        dcp0 += A.x; dcp1 += A.y; dcp2 += A.z; row += A.w;
        a0   += B.x; a1   += B.y; a2   += B.z;
    }

    // dmom = 100*x_i*row - ln2*a'   (a' scaled by 100*log2e)
    const float r100 = 100.0f * row;
    out[3 * i + 0] = fmaf(r100, xi0, -LN2F * a0);
    out[3 * i + 1] = fmaf(r100, xi1, -LN2F * a1);
    out[3 * i + 2] = fmaf(r100, xi2, -LN2F * a2);

    out[3 * NPTS + 3 * i + 0] = dcp0;
    out[3 * NPTS + 3 * i + 1] = dcp1;
    out[3 * NPTS + 3 * i + 2] = dcp2;

    // Reset counter for the next (graph-replayed) call.
    if (threadIdx.x == 0) g_cnt[blockIdx.x] = 0;
}

extern "C" void kernel_launch(void* const* d_in, const int* in_sizes, int n_in,
                              void* d_out, int out_size) {
    const float* mom = (const float*)d_in[0];   // (1, 8192, 3)
    const float* x   = (const float*)d_in[1];   // (1, 8192, 3)
    float* out = (float*)d_out;                 // [dmom | dcp], 49152 floats

    dim3 grid(NIBLK, NSPLIT);                   // (32, 16) blocks
    lddmm_fused<<<grid, TPB>>>(mom, x, out);
}